// round 14
// baseline (speedup 1.0000x reference)
#include <cuda_runtime.h>
#include <cuda_fp16.h>
#include <cstdint>

#define S_DIM 4
#define B_DIM 2
#define N_SEQ 2048
#define C_DIM 1024
#define H_DIM 16
#define D_DIM 64

// ---------------- scratch (device globals; no allocation allowed) -----------
__device__ __half g_x16[S_DIM * B_DIM * N_SEQ * C_DIM];           // [S*B*N, C]
__device__ __half g_wqkv16[C_DIM * 3 * C_DIM];                    // [C, 3C]
__device__ __half g_wproj16[C_DIM * C_DIM];                       // [C, C]
__device__ __half g_q16[B_DIM * H_DIM * N_SEQ * D_DIM];           // [B,H,N,D]
__device__ __half g_k16[S_DIM * B_DIM * H_DIM * N_SEQ * D_DIM];   // [S,B,H,N,D]
__device__ __half g_v16[S_DIM * B_DIM * H_DIM * N_SEQ * D_DIM];   // [S,B,H,N,D]
__device__ __half g_attn16[B_DIM * N_SEQ * C_DIM];                // [B,N,C]

#define DEVI __device__ __forceinline__

// packed fp16x2 2^x
DEVI uint32_t h2ex2(uint32_t x) {
    uint32_t r;
    asm("ex2.approx.f16x2 %0,%1;" : "=r"(r) : "r"(x));
    return r;
}

#define LDMAT4(r0,r1,r2,r3,addr) \
    asm volatile("ldmatrix.sync.aligned.m8n8.x4.shared.b16 {%0,%1,%2,%3},[%4];\n" \
        : "=r"(r0),"=r"(r1),"=r"(r2),"=r"(r3) : "r"(addr))
#define LDMAT4T(r0,r1,r2,r3,addr) \
    asm volatile("ldmatrix.sync.aligned.m8n8.x4.trans.shared.b16 {%0,%1,%2,%3},[%4];\n" \
        : "=r"(r0),"=r"(r1),"=r"(r2),"=r"(r3) : "r"(addr))
// fp32-acc HMMA
#define MMA16816(c,a,b) \
    asm volatile("mma.sync.aligned.m16n8k16.row.col.f32.f16.f16.f32 " \
        "{%0,%1,%2,%3},{%4,%5,%6,%7},{%8,%9},{%0,%1,%2,%3};\n" \
        : "+f"((c)[0]),"+f"((c)[1]),"+f"((c)[2]),"+f"((c)[3]) \
        : "r"((a)[0]),"r"((a)[1]),"r"((a)[2]),"r"((a)[3]),"r"((b)[0]),"r"((b)[1]))
// fp16-acc HMMA
#define MMA16816H(c0,c1,a,b) \
    asm volatile("mma.sync.aligned.m16n8k16.row.col.f16.f16.f16.f16 " \
        "{%0,%1},{%2,%3,%4,%5},{%6,%7},{%0,%1};\n" \
        : "+r"(c0),"+r"(c1) \
        : "r"((a)[0]),"r"((a)[1]),"r"((a)[2]),"r"((a)[3]),"r"((b)[0]),"r"((b)[1]))
#define CPA16(dst,src) \
    asm volatile("cp.async.cg.shared.global [%0],[%1],16;\n" :: "r"(dst),"l"(src))
#define CPA_COMMIT() asm volatile("cp.async.commit_group;\n")
#define CPA_WAIT1()  asm volatile("cp.async.wait_group 1;\n")
#define CPA_WAIT0()  asm volatile("cp.async.wait_group 0;\n")

// ---------------- fused fp32 -> fp16 conversion (x, wqkv, wproj) -----------
#define NX8 (S_DIM * B_DIM * N_SEQ * C_DIM / 8)   // 2097152
#define NW8 (C_DIM * 3 * C_DIM / 8)               // 393216
#define NP8 (C_DIM * C_DIM / 8)                   // 131072

__global__ void f2h_all(const float* __restrict__ x,
                        const float* __restrict__ wqkv,
                        const float* __restrict__ wproj)
{
    int i8 = blockIdx.x * 256 + threadIdx.x;
    const float* s;
    __half* d;
    int off;
    if (i8 < NX8)             { s = x;     d = g_x16;    off = i8; }
    else if (i8 < NX8 + NW8)  { s = wqkv;  d = g_wqkv16; off = i8 - NX8; }
    else                      { s = wproj; d = g_wproj16; off = i8 - NX8 - NW8; }
    int i = off * 8;
    float4 a = *(const float4*)(s + i);
    float4 b = *(const float4*)(s + i + 4);
    __half2 h0 = __floats2half2_rn(a.x, a.y), h1 = __floats2half2_rn(a.z, a.w);
    __half2 h2 = __floats2half2_rn(b.x, b.y), h3 = __floats2half2_rn(b.z, b.w);
    uint4 u;
    u.x = *(uint32_t*)&h0; u.y = *(uint32_t*)&h1;
    u.z = *(uint32_t*)&h2; u.w = *(uint32_t*)&h3;
    *(uint4*)(d + i) = u;
}

// ---------------- GEMM core: 256x128x64 block tile, 512 thr, 3-stage -------
// M=256 halves B-operand traffic per output element (ingest-bound theory).
// 16 warps as 8(m) x 2(n): each warp 32 rows x 64 cols — per-warp code
// identical to the previous 128x128 kernel.
#define G_ASZ (256 * 72)           // 18432 halfs
#define G_BSZ (64 * 136)           //  8704 halfs
#define G_STG (G_ASZ + G_BSZ)      // 27136 halfs = 54272 B
#define G_NK  16
#define GEMM_SMEM (3 * G_STG * 2)  // 162816 B

// one stage: A(256x64) + B(64x128)
#define G_ISSUE(Ag, Bg, LDBv, KT, S) do { \
        _Pragma("unroll") \
        for (int p_ = 0; p_ < 4; p_++) { \
            int idx_ = t + p_ * 512; \
            int r_ = idx_ >> 3, c8_ = (idx_ & 7) * 8; \
            CPA16((uint32_t)__cvta_generic_to_shared(shm + (S) * G_STG + r_ * 72 + c8_), \
                  (Ag) + (size_t)(m0 + r_) * C_DIM + (KT) * 64 + c8_); \
        } \
        _Pragma("unroll") \
        for (int p_ = 0; p_ < 2; p_++) { \
            int idx_ = t + p_ * 512; \
            int kr_ = idx_ >> 4, c_ = (idx_ & 15) * 8; \
            CPA16((uint32_t)__cvta_generic_to_shared(shm + (S) * G_STG + G_ASZ + kr_ * 136 + c_), \
                  (Bg) + (size_t)((KT) * 64 + kr_) * (LDBv) + n0 + c_); \
        } \
        CPA_COMMIT(); \
    } while (0)

#define G_MAINLOOP(Ag, Bg, LDBv) \
    G_ISSUE(Ag, Bg, LDBv, 0, 0); \
    G_ISSUE(Ag, Bg, LDBv, 1, 1); \
    const int aoff0 = (wm + (lane & 15)) * 72 + (lane >> 4) * 8; \
    const int boff0 = (((lane >> 3) & 1) * 8 + (lane & 7)) * 136 + wn + (lane >> 4) * 8; \
    for (int kt = 0; kt < G_NK; kt++) { \
        if (kt + 1 < G_NK) CPA_WAIT1(); else CPA_WAIT0(); \
        __syncthreads(); \
        if (kt + 2 < G_NK) G_ISSUE(Ag, Bg, LDBv, kt + 2, (kt + 2) % 3); \
        const __half* st = shm + (kt % 3) * G_STG; \
        _Pragma("unroll") \
        for (int ks = 0; ks < 4; ks++) { \
            uint32_t a[2][4]; \
            _Pragma("unroll") \
            for (int mi = 0; mi < 2; mi++) { \
                uint32_t ad = (uint32_t)__cvta_generic_to_shared(st + aoff0 + mi * 16 * 72 + ks * 16); \
                LDMAT4(a[mi][0], a[mi][1], a[mi][2], a[mi][3], ad); \
            } \
            uint32_t b[8][2]; \
            _Pragma("unroll") \
            for (int np = 0; np < 4; np++) { \
                uint32_t bd = (uint32_t)__cvta_generic_to_shared(st + G_ASZ + boff0 + np * 16 + ks * 16 * 136); \
                LDMAT4T(b[2 * np][0], b[2 * np][1], b[2 * np + 1][0], b[2 * np + 1][1], bd); \
            } \
            _Pragma("unroll") \
            for (int mi = 0; mi < 2; mi++) \
                _Pragma("unroll") \
                for (int ni = 0; ni < 8; ni++) \
                    MMA16816(acc[mi][ni], a[mi], b[ni]); \
        } \
    }

// ---------------- merged QKV projection GEMM -------------------------------
// 1152 CTAs: bid<1024 -> KV (64 m-tiles x 16 n-tiles, cols [1024,3072));
//            else      -> Q  (16 m-tiles x 8 n-tiles, cols [0,1024)).
__global__ void __launch_bounds__(512, 1)
qkv_gemm(const float* __restrict__ bias)
{
    extern __shared__ __half shm[];
    const int bid = blockIdx.x;
    int m0, n0;
    if (bid < 1024) { m0 = (bid >> 4) * 256; n0 = 1024 + (bid & 15) * 128; }
    else            { int q = bid - 1024; m0 = (q >> 3) * 256; n0 = (q & 7) * 128; }

    const int t = threadIdx.x, lane = t & 31, warp = t >> 5;
    const int wm = (warp >> 1) * 32, wn = (warp & 1) * 64;

    float acc[2][8][4];
#pragma unroll
    for (int i = 0; i < 2; i++)
#pragma unroll
        for (int j = 0; j < 8; j++)
#pragma unroll
            for (int c = 0; c < 4; c++) acc[i][j][c] = 0.f;

    G_MAINLOOP(g_x16, g_wqkv16, 3 * C_DIM)

    const int er = lane >> 2, ec = (lane & 3) * 2;
#pragma unroll
    for (int mi = 0; mi < 2; mi++) {
#pragma unroll
        for (int ni = 0; ni < 8; ni++) {
            int m = m0 + wm + mi * 16 + er;
            int n = n0 + wn + ni * 8 + ec;
            float b0 = bias[n], b1 = bias[n + 1];
            __half2 h0 = __floats2half2_rn(acc[mi][ni][0] + b0, acc[mi][ni][1] + b1);
            __half2 h1 = __floats2half2_rn(acc[mi][ni][2] + b0, acc[mi][ni][3] + b1);
            __half* dst = (n < 1024) ? g_q16 : (n < 2048) ? g_k16 : g_v16;
            int ee = n & 1023;
            int sb = m >> 11, nn = m & 2047;
            int hh = ee >> 6, dd = ee & 63;
            size_t base = (((size_t)sb * H_DIM + hh) * N_SEQ + nn) * D_DIM + dd;
            *(__half2*)&dst[base] = h0;
            *(__half2*)&dst[base + 8 * D_DIM] = h1;
        }
    }
}

// ---------------- output projection GEMM (256x128 tiles) --------------------
__global__ void __launch_bounds__(512, 1)
proj_gemm(const float* __restrict__ bias, float* __restrict__ Cout)
{
    extern __shared__ __half shm[];
    const int t = threadIdx.x, lane = t & 31, warp = t >> 5;
    const int m0 = blockIdx.y * 256, n0 = blockIdx.x * 128;
    const int wm = (warp >> 1) * 32, wn = (warp & 1) * 64;

    float acc[2][8][4];
#pragma unroll
    for (int i = 0; i < 2; i++)
#pragma unroll
        for (int j = 0; j < 8; j++)
#pragma unroll
            for (int c = 0; c < 4; c++) acc[i][j][c] = 0.f;

    G_MAINLOOP(g_attn16, g_wproj16, C_DIM)

    const int er = lane >> 2, ec = (lane & 3) * 2;
#pragma unroll
    for (int mi = 0; mi < 2; mi++) {
#pragma unroll
        for (int ni = 0; ni < 8; ni++) {
            int m = m0 + wm + mi * 16 + er;
            int n = n0 + wn + ni * 8 + ec;
            float b0 = bias[n], b1 = bias[n + 1];
            float2 r0; r0.x = acc[mi][ni][0] + b0; r0.y = acc[mi][ni][1] + b1;
            float2 r1; r1.x = acc[mi][ni][2] + b0; r1.y = acc[mi][ni][3] + b1;
            *(float2*)&Cout[(size_t)m * C_DIM + n] = r0;
            *(float2*)&Cout[(size_t)(m + 8) * C_DIM + n] = r1;
        }
    }
}

// ---------------- HMMA flash attention (unchanged from R11) -----------------
__global__ void __launch_bounds__(256, 2) attn_hmma()
{
    extern __shared__ __half shm[];
    constexpr int QSZ = 128 * 72;
    constexpr int KSZ = 128 * 72;
    constexpr int STG = 2 * KSZ;
    constexpr int NT  = 64;

    const int t = threadIdx.x, lane = t & 31, warp = t >> 5;
    const int q0 = blockIdx.x * 128;
    const int h  = blockIdx.y;
    const int b  = blockIdx.z;

#define KV_ISSUE(J, S) do { \
        int sh_ = (J) >> 4, nn_ = ((J) & 15) * 128; \
        size_t base_ = (((size_t)((sh_ * B_DIM + b) * H_DIM + h)) * N_SEQ + nn_) * D_DIM; \
        const __half* kg_ = g_k16 + base_; \
        const __half* vg_ = g_v16 + base_; \
        _Pragma("unroll") \
        for (int p_ = 0; p_ < 4; p_++) { \
            int idx_ = t + p_ * 256; \
            int r_ = idx_ >> 3, c8_ = (idx_ & 7) * 8; \
            uint32_t dk_ = (uint32_t)__cvta_generic_to_shared(shm + QSZ + (S) * STG + r_ * 72 + c8_); \
            CPA16(dk_, kg_ + (size_t)r_ * 64 + c8_); \
            CPA16(dk_ + KSZ * 2, vg_ + (size_t)r_ * 64 + c8_); \
        } \
        CPA_COMMIT(); \
    } while (0)

    KV_ISSUE(0, 0);

    constexpr float CSC = 0.18033688011112042f;  // 0.125 * log2(e)

    const __half* qb = g_q16 + (((size_t)(b * H_DIM + h)) * N_SEQ + q0) * D_DIM;
    {
        const __half2 csc2 = __floats2half2_rn(CSC, CSC);
#pragma unroll
        for (int p = 0; p < 4; p++) {
            int idx = t + p * 256;
            int r = idx >> 3, c = (idx & 7) * 8;
            uint4 raw = *(const uint4*)&qb[(size_t)r * 64 + c];
            __half2* hp = (__half2*)&raw;
#pragma unroll
            for (int q = 0; q < 4; q++) hp[q] = __hmul2(hp[q], csc2);
            *(uint4*)&shm[r * 72 + c] = raw;
        }
    }
    __syncthreads();

    uint32_t aq[4][4];
    const int qoff0 = (warp * 16 + (lane & 15)) * 72 + (lane >> 4) * 8;
#pragma unroll
    for (int ks = 0; ks < 4; ks++) {
        uint32_t ad = (uint32_t)__cvta_generic_to_shared(shm + qoff0 + ks * 16);
        LDMAT4(aq[ks][0], aq[ks][1], aq[ks][2], aq[ks][3], ad);
    }

    float O[8][4];
#pragma unroll
    for (int i = 0; i < 8; i++)
#pragma unroll
        for (int j = 0; j < 4; j++) O[i][j] = 0.f;
    float lsum0 = 0.f, lsum1 = 0.f;

    const int koff0 = ((lane >> 4) * 8 + (lane & 7)) * 72 + ((lane >> 3) & 1) * 8;
    const int voff0 = (((lane >> 3) & 1) * 8 + (lane & 7)) * 72 + (lane >> 4) * 8;

#define S_STEP(NP, BUF) do { \
        uint32_t s00 = 0, s01 = 0, s10 = 0, s11 = 0; \
        _Pragma("unroll") \
        for (int ks = 0; ks < 4; ks++) { \
            uint32_t bkp[2][2]; \
            uint32_t kd = (uint32_t)__cvta_generic_to_shared(Ks + koff0 + (NP) * 16 * 72 + ks * 16); \
            LDMAT4(bkp[0][0], bkp[0][1], bkp[1][0], bkp[1][1], kd); \
            MMA16816H(s00, s01, aq[ks], bkp[0]); \
            MMA16816H(s10, s11, aq[ks], bkp[1]); \
        } \
        sacc[BUF][0] = s00; sacc[BUF][1] = s01; \
        sacc[BUF][2] = s10; sacc[BUF][3] = s11; \
    } while (0)

    for (int j = 0; j < NT; j++) {
        CPA_WAIT0();
        __syncthreads();
        if (j + 1 < NT) KV_ISSUE(j + 1, (j + 1) & 1);

        const __half* Ks = shm + QSZ + (j & 1) * STG;
        const __half* Vs = Ks + KSZ;

        uint32_t sacc[2][4];
        uint32_t ls0 = 0, ls1 = 0;

        S_STEP(0, 0);
#pragma unroll
        for (int np = 0; np < 8; np++) {
            const int buf = np & 1;
            if (np + 1 < 8) S_STEP(np + 1, buf ^ 1);

            uint32_t ap[4];
            ap[0] = h2ex2(sacc[buf][0]);
            ap[1] = h2ex2(sacc[buf][1]);
            ap[2] = h2ex2(sacc[buf][2]);
            ap[3] = h2ex2(sacc[buf][3]);
            {
                __half2* l0 = (__half2*)&ls0;
                __half2* l1 = (__half2*)&ls1;
                *l0 = __hadd2(*l0, __hadd2(*(__half2*)&ap[0], *(__half2*)&ap[2]));
                *l1 = __hadd2(*l1, __hadd2(*(__half2*)&ap[1], *(__half2*)&ap[3]));
            }

            uint32_t bv[8][2];
#pragma unroll
            for (int np2 = 0; np2 < 4; np2++) {
                uint32_t vd = (uint32_t)__cvta_generic_to_shared(Vs + voff0 + np * 16 * 72 + np2 * 16);
                LDMAT4T(bv[2 * np2][0], bv[2 * np2][1], bv[2 * np2 + 1][0], bv[2 * np2 + 1][1], vd);
            }
#pragma unroll
            for (int ni = 0; ni < 8; ni++)
                MMA16816(O[ni], ap, bv[ni]);
        }

        {
            __half2 l0 = *(__half2*)&ls0, l1 = *(__half2*)&ls1;
            lsum0 += __low2float(l0) + __high2float(l0);
            lsum1 += __low2float(l1) + __high2float(l1);
        }
    }
#undef S_STEP
#undef KV_ISSUE

    lsum0 += __shfl_xor_sync(0xffffffffu, lsum0, 1);
    lsum0 += __shfl_xor_sync(0xffffffffu, lsum0, 2);
    lsum1 += __shfl_xor_sync(0xffffffffu, lsum1, 1);
    lsum1 += __shfl_xor_sync(0xffffffffu, lsum1, 2);

    float inv0 = 1.f / lsum0, inv1 = 1.f / lsum1;
    const int er = lane >> 2, ec = (lane & 3) * 2;
    __half* ob = g_attn16 + ((size_t)(b * N_SEQ + q0 + warp * 16) * C_DIM) + h * D_DIM;
#pragma unroll
    for (int ni = 0; ni < 8; ni++) {
        int cc = ni * 8 + ec;
        __half2 h0 = __floats2half2_rn(O[ni][0] * inv0, O[ni][1] * inv0);
        __half2 h1 = __floats2half2_rn(O[ni][2] * inv1, O[ni][3] * inv1);
        *(__half2*)&ob[(size_t)er * C_DIM + cc] = h0;
        *(__half2*)&ob[(size_t)(er + 8) * C_DIM + cc] = h1;
    }
}

// ---------------------------------------------------------------------------
extern "C" void kernel_launch(void* const* d_in, const int* in_sizes, int n_in,
                              void* d_out, int out_size)
{
    const float* bqkv  = (const float*)d_in[2];
    const float* bproj = (const float*)d_in[4];
    float* out = (float*)d_out;
    (void)in_sizes; (void)n_in; (void)out_size;

    constexpr int ATTN_SMEM = (128 * 72 + 2 * 2 * 128 * 72) * 2;   // 92160 B

    cudaFuncSetAttribute(qkv_gemm,  cudaFuncAttributeMaxDynamicSharedMemorySize, GEMM_SMEM);
    cudaFuncSetAttribute(proj_gemm, cudaFuncAttributeMaxDynamicSharedMemorySize, GEMM_SMEM);
    cudaFuncSetAttribute(attn_hmma, cudaFuncAttributeMaxDynamicSharedMemorySize, ATTN_SMEM);

    f2h_all<<<NX8 / 256 + NW8 / 256 + NP8 / 256, 256>>>(
        (const float*)d_in[0], (const float*)d_in[1], (const float*)d_in[3]);

    qkv_gemm<<<1152, 512, GEMM_SMEM>>>(bqkv);
    attn_hmma<<<dim3(N_SEQ / 128, H_DIM, B_DIM), 256, ATTN_SMEM>>>();
    proj_gemm<<<dim3(8, 16), 512, GEMM_SMEM>>>(bproj, out);
}

// round 17
// speedup vs baseline: 1.0047x; 1.0047x over previous
#include <cuda_runtime.h>
#include <cuda_fp16.h>
#include <cstdint>

#define S_DIM 4
#define B_DIM 2
#define N_SEQ 2048
#define C_DIM 1024
#define H_DIM 16
#define D_DIM 64

// ---------------- scratch (device globals; no allocation allowed) -----------
__device__ __half g_x16[S_DIM * B_DIM * N_SEQ * C_DIM];           // [S*B*N, C]
__device__ __half g_wqkv16[C_DIM * 3 * C_DIM];                    // [C, 3C]
__device__ __half g_wproj16[C_DIM * C_DIM];                       // [C, C]
__device__ __half g_q16[B_DIM * H_DIM * N_SEQ * D_DIM];           // [B,H,N,D]
__device__ __half g_k16[S_DIM * B_DIM * H_DIM * N_SEQ * D_DIM];   // [S,B,H,N,D]
__device__ __half g_v16[S_DIM * B_DIM * H_DIM * N_SEQ * D_DIM];   // [S,B,H,N,D]
__device__ __half g_attn16[B_DIM * N_SEQ * C_DIM];                // [B,N,C]

#define DEVI __device__ __forceinline__

// packed fp16x2 2^x
DEVI uint32_t h2ex2(uint32_t x) {
    uint32_t r;
    asm("ex2.approx.f16x2 %0,%1;" : "=r"(r) : "r"(x));
    return r;
}

#define LDMAT4(r0,r1,r2,r3,addr) \
    asm volatile("ldmatrix.sync.aligned.m8n8.x4.shared.b16 {%0,%1,%2,%3},[%4];\n" \
        : "=r"(r0),"=r"(r1),"=r"(r2),"=r"(r3) : "r"(addr))
#define LDMAT4T(r0,r1,r2,r3,addr) \
    asm volatile("ldmatrix.sync.aligned.m8n8.x4.trans.shared.b16 {%0,%1,%2,%3},[%4];\n" \
        : "=r"(r0),"=r"(r1),"=r"(r2),"=r"(r3) : "r"(addr))
// fp32-acc HMMA
#define MMA16816(c,a,b) \
    asm volatile("mma.sync.aligned.m16n8k16.row.col.f32.f16.f16.f32 " \
        "{%0,%1,%2,%3},{%4,%5,%6,%7},{%8,%9},{%0,%1,%2,%3};\n" \
        : "+f"((c)[0]),"+f"((c)[1]),"+f"((c)[2]),"+f"((c)[3]) \
        : "r"((a)[0]),"r"((a)[1]),"r"((a)[2]),"r"((a)[3]),"r"((b)[0]),"r"((b)[1]))
// fp16-acc HMMA
#define MMA16816H(c0,c1,a,b) \
    asm volatile("mma.sync.aligned.m16n8k16.row.col.f16.f16.f16.f16 " \
        "{%0,%1},{%2,%3,%4,%5},{%6,%7},{%0,%1};\n" \
        : "+r"(c0),"+r"(c1) \
        : "r"((a)[0]),"r"((a)[1]),"r"((a)[2]),"r"((a)[3]),"r"((b)[0]),"r"((b)[1]))
#define CPA16(dst,src) \
    asm volatile("cp.async.cg.shared.global [%0],[%1],16;\n" :: "r"(dst),"l"(src))
#define CPA_COMMIT() asm volatile("cp.async.commit_group;\n")
#define CPA_WAIT1()  asm volatile("cp.async.wait_group 1;\n")
#define CPA_WAIT0()  asm volatile("cp.async.wait_group 0;\n")

// ---------------- fused fp32 -> fp16 conversion (x, wqkv, wproj) -----------
#define NX8 (S_DIM * B_DIM * N_SEQ * C_DIM / 8)   // 2097152
#define NW8 (C_DIM * 3 * C_DIM / 8)               // 393216
#define NP8 (C_DIM * C_DIM / 8)                   // 131072

__global__ void f2h_all(const float* __restrict__ x,
                        const float* __restrict__ wqkv,
                        const float* __restrict__ wproj)
{
    int i8 = blockIdx.x * 256 + threadIdx.x;
    const float* s;
    __half* d;
    int off;
    if (i8 < NX8)             { s = x;     d = g_x16;    off = i8; }
    else if (i8 < NX8 + NW8)  { s = wqkv;  d = g_wqkv16; off = i8 - NX8; }
    else                      { s = wproj; d = g_wproj16; off = i8 - NX8 - NW8; }
    int i = off * 8;
    float4 a = *(const float4*)(s + i);
    float4 b = *(const float4*)(s + i + 4);
    __half2 h0 = __floats2half2_rn(a.x, a.y), h1 = __floats2half2_rn(a.z, a.w);
    __half2 h2 = __floats2half2_rn(b.x, b.y), h3 = __floats2half2_rn(b.z, b.w);
    uint4 u;
    u.x = *(uint32_t*)&h0; u.y = *(uint32_t*)&h1;
    u.z = *(uint32_t*)&h2; u.w = *(uint32_t*)&h3;
    *(uint4*)(d + i) = u;
}

// ---------------- GEMM core: 128x128x64 block tile, 3-stage (R12 config) ---
#define G_ASZ (128 * 72)
#define G_BSZ (64 * 136)
#define G_STG (G_ASZ + G_BSZ)      // 17920 halfs = 35840 B
#define G_NK  16
#define GEMM_SMEM (3 * G_STG * 2)  // 107520 B

#define G_ISSUE(Ag, Bg, LDBv, KT, S) do { \
        _Pragma("unroll") \
        for (int p_ = 0; p_ < 4; p_++) { \
            int idx_ = t + p_ * 256; \
            int r_ = idx_ >> 3, c8_ = (idx_ & 7) * 8; \
            CPA16((uint32_t)__cvta_generic_to_shared(shm + (S) * G_STG + r_ * 72 + c8_), \
                  (Ag) + (size_t)(m0 + r_) * C_DIM + (KT) * 64 + c8_); \
        } \
        _Pragma("unroll") \
        for (int p_ = 0; p_ < 4; p_++) { \
            int idx_ = t + p_ * 256; \
            int kr_ = idx_ >> 4, c_ = (idx_ & 15) * 8; \
            CPA16((uint32_t)__cvta_generic_to_shared(shm + (S) * G_STG + G_ASZ + kr_ * 136 + c_), \
                  (Bg) + (size_t)((KT) * 64 + kr_) * (LDBv) + n0 + c_); \
        } \
        CPA_COMMIT(); \
    } while (0)

#define G_MAINLOOP(Ag, Bg, LDBv) \
    G_ISSUE(Ag, Bg, LDBv, 0, 0); \
    G_ISSUE(Ag, Bg, LDBv, 1, 1); \
    const int aoff0 = (wm + (lane & 15)) * 72 + (lane >> 4) * 8; \
    const int boff0 = (((lane >> 3) & 1) * 8 + (lane & 7)) * 136 + wn + (lane >> 4) * 8; \
    for (int kt = 0; kt < G_NK; kt++) { \
        if (kt + 1 < G_NK) CPA_WAIT1(); else CPA_WAIT0(); \
        __syncthreads(); \
        if (kt + 2 < G_NK) G_ISSUE(Ag, Bg, LDBv, kt + 2, (kt + 2) % 3); \
        const __half* st = shm + (kt % 3) * G_STG; \
        _Pragma("unroll") \
        for (int ks = 0; ks < 4; ks++) { \
            uint32_t a[2][4]; \
            _Pragma("unroll") \
            for (int mi = 0; mi < 2; mi++) { \
                uint32_t ad = (uint32_t)__cvta_generic_to_shared(st + aoff0 + mi * 16 * 72 + ks * 16); \
                LDMAT4(a[mi][0], a[mi][1], a[mi][2], a[mi][3], ad); \
            } \
            uint32_t b[8][2]; \
            _Pragma("unroll") \
            for (int np = 0; np < 4; np++) { \
                uint32_t bd = (uint32_t)__cvta_generic_to_shared(st + G_ASZ + boff0 + np * 16 + ks * 16 * 136); \
                LDMAT4T(b[2 * np][0], b[2 * np][1], b[2 * np + 1][0], b[2 * np + 1][1], bd); \
            } \
            _Pragma("unroll") \
            for (int mi = 0; mi < 2; mi++) \
                _Pragma("unroll") \
                for (int ni = 0; ni < 8; ni++) \
                    MMA16816(acc[mi][ni], a[mi], b[ni]); \
        } \
    }

// ---------------- merged QKV projection GEMM (R12 config) -------------------
__global__ void __launch_bounds__(256, 2)
qkv_gemm(const float* __restrict__ bias)
{
    extern __shared__ __half shm[];
    const int bid = blockIdx.x;
    int m0, n0;
    if (bid < 2048) { m0 = (bid >> 4) * 128; n0 = 1024 + (bid & 15) * 128; }
    else            { int q = bid - 2048; m0 = (q >> 3) * 128; n0 = (q & 7) * 128; }

    const int t = threadIdx.x, lane = t & 31, warp = t >> 5;
    const int wm = (warp >> 1) * 32, wn = (warp & 1) * 64;

    float acc[2][8][4];
#pragma unroll
    for (int i = 0; i < 2; i++)
#pragma unroll
        for (int j = 0; j < 8; j++)
#pragma unroll
            for (int c = 0; c < 4; c++) acc[i][j][c] = 0.f;

    G_MAINLOOP(g_x16, g_wqkv16, 3 * C_DIM)

    const int er = lane >> 2, ec = (lane & 3) * 2;
#pragma unroll
    for (int mi = 0; mi < 2; mi++) {
#pragma unroll
        for (int ni = 0; ni < 8; ni++) {
            int m = m0 + wm + mi * 16 + er;
            int n = n0 + wn + ni * 8 + ec;
            float b0 = bias[n], b1 = bias[n + 1];
            __half2 h0 = __floats2half2_rn(acc[mi][ni][0] + b0, acc[mi][ni][1] + b1);
            __half2 h1 = __floats2half2_rn(acc[mi][ni][2] + b0, acc[mi][ni][3] + b1);
            __half* dst = (n < 1024) ? g_q16 : (n < 2048) ? g_k16 : g_v16;
            int ee = n & 1023;
            int sb = m >> 11, nn = m & 2047;
            int hh = ee >> 6, dd = ee & 63;
            size_t base = (((size_t)sb * H_DIM + hh) * N_SEQ + nn) * D_DIM + dd;
            *(__half2*)&dst[base] = h0;
            *(__half2*)&dst[base + 8 * D_DIM] = h1;
        }
    }
}

// ---------------- output projection GEMM (R12 config) -----------------------
__global__ void __launch_bounds__(256, 2)
proj_gemm(const float* __restrict__ bias, float* __restrict__ Cout)
{
    extern __shared__ __half shm[];
    const int t = threadIdx.x, lane = t & 31, warp = t >> 5;
    const int m0 = blockIdx.y * 128, n0 = blockIdx.x * 128;
    const int wm = (warp >> 1) * 32, wn = (warp & 1) * 64;

    float acc[2][8][4];
#pragma unroll
    for (int i = 0; i < 2; i++)
#pragma unroll
        for (int j = 0; j < 8; j++)
#pragma unroll
            for (int c = 0; c < 4; c++) acc[i][j][c] = 0.f;

    G_MAINLOOP(g_attn16, g_wproj16, C_DIM)

    const int er = lane >> 2, ec = (lane & 3) * 2;
#pragma unroll
    for (int mi = 0; mi < 2; mi++) {
#pragma unroll
        for (int ni = 0; ni < 8; ni++) {
            int m = m0 + wm + mi * 16 + er;
            int n = n0 + wn + ni * 8 + ec;
            float b0 = bias[n], b1 = bias[n + 1];
            float2 r0; r0.x = acc[mi][ni][0] + b0; r0.y = acc[mi][ni][1] + b1;
            float2 r1; r1.x = acc[mi][ni][2] + b0; r1.y = acc[mi][ni][3] + b1;
            *(float2*)&Cout[(size_t)m * C_DIM + n] = r0;
            *(float2*)&Cout[(size_t)(m + 8) * C_DIM + n] = r1;
        }
    }
}

// ---------------- HMMA flash attention: token-split warps -------------------
// 8 warps = 4(q) x 2(k): warp owns 32 Q rows (resident frags) x 64 tokens of
// each KV tile. Each K/V byte read by 4 warps (was 8) -> smem traffic ~halved.
// Partial O (per k-half) kept in regs across all tiles; one smem reduction at
// the end merges halves and normalizes. No online max (scores bounded).
__global__ void __launch_bounds__(256, 2) attn_hmma()
{
    extern __shared__ __half shm[];
    constexpr int QSZ = 128 * 72;
    constexpr int KSZ = 128 * 72;
    constexpr int STG = 2 * KSZ;
    constexpr int NT  = 64;

    const int t = threadIdx.x, lane = t & 31, warp = t >> 5;
    const int qi = warp >> 1;      // 0..3: Q row group (32 rows)
    const int kj = warp & 1;       // 0..1: token half (64 tokens)
    const int q0 = blockIdx.x * 128;
    const int h  = blockIdx.y;
    const int b  = blockIdx.z;

#define KV_ISSUE(J, S) do { \
        int sh_ = (J) >> 4, nn_ = ((J) & 15) * 128; \
        size_t base_ = (((size_t)((sh_ * B_DIM + b) * H_DIM + h)) * N_SEQ + nn_) * D_DIM; \
        const __half* kg_ = g_k16 + base_; \
        const __half* vg_ = g_v16 + base_; \
        _Pragma("unroll") \
        for (int p_ = 0; p_ < 4; p_++) { \
            int idx_ = t + p_ * 256; \
            int r_ = idx_ >> 3, c8_ = (idx_ & 7) * 8; \
            uint32_t dk_ = (uint32_t)__cvta_generic_to_shared(shm + QSZ + (S) * STG + r_ * 72 + c8_); \
            CPA16(dk_, kg_ + (size_t)r_ * 64 + c8_); \
            CPA16(dk_ + KSZ * 2, vg_ + (size_t)r_ * 64 + c8_); \
        } \
        CPA_COMMIT(); \
    } while (0)

    KV_ISSUE(0, 0);

    constexpr float CSC = 0.18033688011112042f;  // 0.125 * log2(e)

    // Q tile -> smem, pre-scaled
    const __half* qb = g_q16 + (((size_t)(b * H_DIM + h)) * N_SEQ + q0) * D_DIM;
    {
        const __half2 csc2 = __floats2half2_rn(CSC, CSC);
#pragma unroll
        for (int p = 0; p < 4; p++) {
            int idx = t + p * 256;
            int r = idx >> 3, c = (idx & 7) * 8;
            uint4 raw = *(const uint4*)&qb[(size_t)r * 64 + c];
            __half2* hp = (__half2*)&raw;
#pragma unroll
            for (int q = 0; q < 4; q++) hp[q] = __hmul2(hp[q], csc2);
            *(uint4*)&shm[r * 72 + c] = raw;
        }
    }
    __syncthreads();

    // resident Q fragments: rows [qi*32, qi*32+32), 2 m-blocks of 16
    uint32_t aq[2][4][4];
#pragma unroll
    for (int mi = 0; mi < 2; mi++) {
        const int qoff = (qi * 32 + mi * 16 + (lane & 15)) * 72 + (lane >> 4) * 8;
#pragma unroll
        for (int ks = 0; ks < 4; ks++) {
            uint32_t ad = (uint32_t)__cvta_generic_to_shared(shm + qoff + ks * 16);
            LDMAT4(aq[mi][ks][0], aq[mi][ks][1], aq[mi][ks][2], aq[mi][ks][3], ad);
        }
    }

    float O[2][8][4];   // partial over this warp's 64-token half
#pragma unroll
    for (int mi = 0; mi < 2; mi++)
#pragma unroll
        for (int i = 0; i < 8; i++)
#pragma unroll
            for (int j = 0; j < 4; j++) O[mi][i][j] = 0.f;
    float lsum[2][2];   // [mi][er/er+8] partial row sums
    lsum[0][0] = lsum[0][1] = lsum[1][0] = lsum[1][1] = 0.f;

    const int koff0 = ((lane >> 4) * 8 + (lane & 7)) * 72 + ((lane >> 3) & 1) * 8;
    const int voff0 = (((lane >> 3) & 1) * 8 + (lane & 7)) * 72 + (lane >> 4) * 8;
    const int tokbase = kj * 64;   // this warp's token half within the tile

    for (int j = 0; j < NT; j++) {
        CPA_WAIT0();
        __syncthreads();
        if (j + 1 < NT) KV_ISSUE(j + 1, (j + 1) & 1);

        const __half* Ks = shm + QSZ + (j & 1) * STG;
        const __half* Vs = Ks + KSZ;

        uint32_t ls0 = 0, ls1 = 0, ls2 = 0, ls3 = 0;  // fp16x2 tile sums [mi][row]

#pragma unroll
        for (int np = 0; np < 4; np++) {
            const int trow = tokbase + np * 16;

            // ---- S: P(32q x 16tok) over d=64, fp16 acc ----
            uint32_t s[2][4];
#pragma unroll
            for (int mi = 0; mi < 2; mi++) { s[mi][0] = s[mi][1] = s[mi][2] = s[mi][3] = 0; }
#pragma unroll
            for (int ks = 0; ks < 4; ks++) {
                uint32_t bkp[2][2];
                uint32_t kd = (uint32_t)__cvta_generic_to_shared(Ks + koff0 + trow * 72 + ks * 16);
                LDMAT4(bkp[0][0], bkp[0][1], bkp[1][0], bkp[1][1], kd);
#pragma unroll
                for (int mi = 0; mi < 2; mi++) {
                    MMA16816H(s[mi][0], s[mi][1], aq[mi][ks], bkp[0]);
                    MMA16816H(s[mi][2], s[mi][3], aq[mi][ks], bkp[1]);
                }
            }

            // ---- exp (fp16x2) + tile-local row sums ----
            uint32_t ap[2][4];
#pragma unroll
            for (int mi = 0; mi < 2; mi++) {
                ap[mi][0] = h2ex2(s[mi][0]);
                ap[mi][1] = h2ex2(s[mi][1]);
                ap[mi][2] = h2ex2(s[mi][2]);
                ap[mi][3] = h2ex2(s[mi][3]);
            }
            {
                __half2* p;
                p = (__half2*)&ls0; *p = __hadd2(*p, __hadd2(*(__half2*)&ap[0][0], *(__half2*)&ap[0][2]));
                p = (__half2*)&ls1; *p = __hadd2(*p, __hadd2(*(__half2*)&ap[0][1], *(__half2*)&ap[0][3]));
                p = (__half2*)&ls2; *p = __hadd2(*p, __hadd2(*(__half2*)&ap[1][0], *(__half2*)&ap[1][2]));
                p = (__half2*)&ls3; *p = __hadd2(*p, __hadd2(*(__half2*)&ap[1][1], *(__half2*)&ap[1][3]));
            }

            // ---- PV: O += P(.,16tok) x V(16tok, 64d), fp32 acc ----
#pragma unroll
            for (int np2 = 0; np2 < 4; np2++) {
                uint32_t bv0, bv1, bv2, bv3;
                uint32_t vd = (uint32_t)__cvta_generic_to_shared(Vs + voff0 + trow * 72 + np2 * 16);
                LDMAT4T(bv0, bv1, bv2, bv3, vd);
                uint32_t bvA[2] = { bv0, bv1 };
                uint32_t bvB[2] = { bv2, bv3 };
#pragma unroll
                for (int mi = 0; mi < 2; mi++) {
                    MMA16816(O[mi][2 * np2],     ap[mi], bvA);
                    MMA16816(O[mi][2 * np2 + 1], ap[mi], bvB);
                }
            }
        }

        // flush tile fp16 sums to fp32
        {
            __half2 v;
            v = *(__half2*)&ls0; lsum[0][0] += __low2float(v) + __high2float(v);
            v = *(__half2*)&ls1; lsum[0][1] += __low2float(v) + __high2float(v);
            v = *(__half2*)&ls2; lsum[1][0] += __low2float(v) + __high2float(v);
            v = *(__half2*)&ls3; lsum[1][1] += __low2float(v) + __high2float(v);
        }
    }
#undef KV_ISSUE

    // reduce lsum over the 4 lanes sharing each row (token-column quads)
#pragma unroll
    for (int mi = 0; mi < 2; mi++)
#pragma unroll
        for (int r = 0; r < 2; r++) {
            lsum[mi][r] += __shfl_xor_sync(0xffffffffu, lsum[mi][r], 1);
            lsum[mi][r] += __shfl_xor_sync(0xffffffffu, lsum[mi][r], 2);
        }

    // ---- cross-warp merge of the two token halves ----
    // smem reuse: osm[128][64] fp32 (32KB) + lsm[128] fp32
    float* osm = (float*)shm;
    float* lsm = osm + 128 * 64;
    const int er = lane >> 2, ec = (lane & 3) * 2;

    __syncthreads();   // all warps done with Q/KV smem

    if (kj == 1) {
#pragma unroll
        for (int mi = 0; mi < 2; mi++) {
            int r0 = qi * 32 + mi * 16 + er;
#pragma unroll
            for (int ni = 0; ni < 8; ni++) {
                int cc = ni * 8 + ec;
                osm[r0 * 64 + cc]           = O[mi][ni][0];
                osm[r0 * 64 + cc + 1]       = O[mi][ni][1];
                osm[(r0 + 8) * 64 + cc]     = O[mi][ni][2];
                osm[(r0 + 8) * 64 + cc + 1] = O[mi][ni][3];
            }
            if ((lane & 3) == 0) {
                lsm[r0]     = lsum[mi][0];
                lsm[r0 + 8] = lsum[mi][1];
            }
        }
    }
    __syncthreads();

    if (kj == 0) {
        __half* ob = g_attn16 + ((size_t)(b * N_SEQ + q0)) * C_DIM + h * D_DIM;
#pragma unroll
        for (int mi = 0; mi < 2; mi++) {
            int r0 = qi * 32 + mi * 16 + er;
            float inv0 = 1.f / (lsum[mi][0] + lsm[r0]);
            float inv1 = 1.f / (lsum[mi][1] + lsm[r0 + 8]);
#pragma unroll
            for (int ni = 0; ni < 8; ni++) {
                int cc = ni * 8 + ec;
                float v00 = (O[mi][ni][0] + osm[r0 * 64 + cc])           * inv0;
                float v01 = (O[mi][ni][1] + osm[r0 * 64 + cc + 1])       * inv0;
                float v10 = (O[mi][ni][2] + osm[(r0 + 8) * 64 + cc])     * inv1;
                float v11 = (O[mi][ni][3] + osm[(r0 + 8) * 64 + cc + 1]) * inv1;
                *(__half2*)&ob[(size_t)r0 * C_DIM + cc]       = __floats2half2_rn(v00, v01);
                *(__half2*)&ob[(size_t)(r0 + 8) * C_DIM + cc] = __floats2half2_rn(v10, v11);
            }
        }
    }
}

// ---------------------------------------------------------------------------
extern "C" void kernel_launch(void* const* d_in, const int* in_sizes, int n_in,
                              void* d_out, int out_size)
{
    const float* bqkv  = (const float*)d_in[2];
    const float* bproj = (const float*)d_in[4];
    float* out = (float*)d_out;
    (void)in_sizes; (void)n_in; (void)out_size;

    constexpr int ATTN_SMEM = (128 * 72 + 2 * 2 * 128 * 72) * 2;   // 92160 B

    cudaFuncSetAttribute(qkv_gemm,  cudaFuncAttributeMaxDynamicSharedMemorySize, GEMM_SMEM);
    cudaFuncSetAttribute(proj_gemm, cudaFuncAttributeMaxDynamicSharedMemorySize, GEMM_SMEM);
    cudaFuncSetAttribute(attn_hmma, cudaFuncAttributeMaxDynamicSharedMemorySize, ATTN_SMEM);

    f2h_all<<<NX8 / 256 + NW8 / 256 + NP8 / 256, 256>>>(
        (const float*)d_in[0], (const float*)d_in[1], (const float*)d_in[3]);

    qkv_gemm<<<2304, 256, GEMM_SMEM>>>(bqkv);
    attn_hmma<<<dim3(N_SEQ / 128, H_DIM, B_DIM), 256, ATTN_SMEM>>>();
    proj_gemm<<<dim3(8, 32), 256, GEMM_SMEM>>>(bproj, out);
}